// round 13
// baseline (speedup 1.0000x reference)
#include <cuda_runtime.h>
#include <cuda_bf16.h>
#include <cstdint>

// AttentionLayer_50989851738889 — TERMINAL KERNEL (session converged R12)
//
// Mathematical reduction (verified bit-exact, rel_err = 0.0 across all rounds):
//   a = e / sum(e, axis=-1, keepdims=True) over a SIZE-1 axis -> a = e/e = 1.0
//   exactly (g = sum_u tanh(.)*Wa[u] bounded => e finite nonzero; IEEE
//   x/x == 1.0). v = a * inputs == inputs bit-for-bit. Output is a pure copy
//   of d_in[0] (B*L*D = 2097152 fp32 = 8 MB).
//
// Convergence evidence: totals 6.62-6.66us across MLP depth 1..16 and grids
// 128..2048 CTAs, while kernel time varied 5.76-6.24us — the floor is fixed
// launch + graph-replay overhead, not the copy (all mem pipes <20% busy,
// working set L2-resident in timed replays). CE/memcpy-node path measured at
// 7.65us (worse). This config: MLP=8, 512 CTAs x 128 threads, exact single
// wave, full SM coverage — tied-best total 6.624us.

__global__ void __launch_bounds__(128) copy_kernel_v4x8_b128(
    const float4* __restrict__ src, float4* __restrict__ dst, int n4) {
    const int t = blockIdx.x * blockDim.x + threadIdx.x;
    const int s = gridDim.x * blockDim.x;  // 65536

    if (8 * s == n4) {
        // 8 independent front-batched LDG.128 per thread
        float4 r0 = src[t];
        float4 r1 = src[t + s];
        float4 r2 = src[t + 2 * s];
        float4 r3 = src[t + 3 * s];
        float4 r4 = src[t + 4 * s];
        float4 r5 = src[t + 5 * s];
        float4 r6 = src[t + 6 * s];
        float4 r7 = src[t + 7 * s];
        dst[t]         = r0;
        dst[t + s]     = r1;
        dst[t + 2 * s] = r2;
        dst[t + 3 * s] = r3;
        dst[t + 4 * s] = r4;
        dst[t + 5 * s] = r5;
        dst[t + 6 * s] = r6;
        dst[t + 7 * s] = r7;
    } else {
        // Generic fallback (never taken for the fixed shape)
        for (int i = t; i < n4; i += s) dst[i] = src[i];
    }
}

extern "C" void kernel_launch(void* const* d_in, const int* in_sizes, int n_in,
                              void* d_out, int out_size) {
    const float4* src = (const float4*)d_in[0];
    float4* dst = (float4*)d_out;

    int n4 = out_size >> 2;  // 524288 float4

    const int threads = 128;
    const int blocks = 512;  // 512*128*8 == 524288 exactly; single wave, all SMs
    copy_kernel_v4x8_b128<<<blocks, threads>>>(src, dst, n4);
}